// round 9
// baseline (speedup 1.0000x reference)
#include <cuda_runtime.h>
#include <cuda_bf16.h>
#include <cstdint>

#define BATCH 4
#define SEQ   2048
#define DMODEL 1024
#define NHEAD 16
#define DHEAD 64
#define MTOT  (BATCH*SEQ)   // 8192

// ---------------- scratch (static device globals; no runtime alloc) ----------
__device__ __nv_bfloat16 g_xb [MTOT*DMODEL];            // x in bf16
__device__ __nv_bfloat16 g_Qb [BATCH*NHEAD*SEQ*DHEAD];  // [B,H,S,DH] bf16
__device__ __nv_bfloat16 g_Kb [BATCH*NHEAD*SEQ*DHEAD];
__device__ __nv_bfloat16 g_Vb [BATCH*NHEAD*SEQ*DHEAD];
__device__ __nv_bfloat16 g_ctxb[MTOT*DMODEL];           // attention out, bf16
__device__ __nv_bfloat16 g_Wtb[4*DMODEL*DMODEL];        // transposed bf16 weights
__device__ float         g_h  [MTOT*DMODEL];            // O-proj out, fp32
__device__ float         g_msc[BATCH*SEQ];              // mask * log2(e)

// ---------------- low-level helpers ------------------------------------------
__device__ __forceinline__ uint32_t smem_u32(const void* p) {
    uint32_t a;
    asm("{ .reg .u64 t; cvta.to.shared.u64 t, %1; cvt.u32.u64 %0, t; }" : "=r"(a) : "l"(p));
    return a;
}
__device__ __forceinline__ void cpasync16(uint32_t dst, const void* src) {
    asm volatile("cp.async.cg.shared.global [%0], [%1], 16;" :: "r"(dst), "l"(src));
}
__device__ __forceinline__ void cp_commit() { asm volatile("cp.async.commit_group;"); }
__device__ __forceinline__ void cp_wait0()  { asm volatile("cp.async.wait_group 0;"); }
__device__ __forceinline__ void cp_wait1()  { asm volatile("cp.async.wait_group 1;"); }

__device__ __forceinline__ float ex2(float x) {
    float y; asm("ex2.approx.f32 %0, %1;" : "=f"(y) : "f"(x)); return y;
}

__device__ __forceinline__ void mma_bf16(float c[4], const uint32_t a[4],
                                         uint32_t b0, uint32_t b1) {
    asm volatile(
        "mma.sync.aligned.m16n8k16.row.col.f32.bf16.bf16.f32 "
        "{%0,%1,%2,%3}, {%4,%5,%6,%7}, {%8,%9}, {%0,%1,%2,%3};"
        : "+f"(c[0]), "+f"(c[1]), "+f"(c[2]), "+f"(c[3])
        : "r"(a[0]), "r"(a[1]), "r"(a[2]), "r"(a[3]), "r"(b0), "r"(b1));
}
__device__ __forceinline__ void ldsm_x4(uint32_t& r0, uint32_t& r1,
                                        uint32_t& r2, uint32_t& r3, uint32_t addr) {
    asm volatile("ldmatrix.sync.aligned.m8n8.x4.shared.b16 {%0,%1,%2,%3}, [%4];"
        : "=r"(r0), "=r"(r1), "=r"(r2), "=r"(r3) : "r"(addr));
}
__device__ __forceinline__ void ldsm_x4_t(uint32_t& r0, uint32_t& r1,
                                          uint32_t& r2, uint32_t& r3, uint32_t addr) {
    asm volatile("ldmatrix.sync.aligned.m8n8.x4.trans.shared.b16 {%0,%1,%2,%3}, [%4];"
        : "=r"(r0), "=r"(r1), "=r"(r2), "=r"(r3) : "r"(addr));
}
__device__ __forceinline__ uint32_t pack_bf16(float lo, float hi) {
    __nv_bfloat162 t = __float22bfloat162_rn(make_float2(lo, hi));
    return *reinterpret_cast<uint32_t*>(&t);
}

// ---------------- fp32 -> bf16 convert ----------------------------------------
__global__ __launch_bounds__(256) void cvt_kernel(
    const float* __restrict__ x, __nv_bfloat162* __restrict__ o)
{
    size_t i = (size_t)blockIdx.x * 256 + threadIdx.x;   // over float4
    float4 v = ((const float4*)x)[i];
    o[2 * i]     = __float22bfloat162_rn(make_float2(v.x, v.y));
    o[2 * i + 1] = __float22bfloat162_rn(make_float2(v.z, v.w));
}

// ---------------- mask prescale: m * log2(e) ----------------------------------
__global__ __launch_bounds__(256) void mask_kernel(
    const float* __restrict__ m, float* __restrict__ o)
{
    int i = blockIdx.x * 256 + threadIdx.x;
    o[i] = m[i] * 1.4426950408889634f;
}

// -------- transpose + convert all 4 weights: W[K][N] fp32 -> Wt[N][K] bf16 ----
__global__ __launch_bounds__(256) void tr_kernel(
    const float* __restrict__ s0, const float* __restrict__ s1,
    const float* __restrict__ s2, const float* __restrict__ s3,
    __nv_bfloat16* __restrict__ dstb)
{
    const float* src = (blockIdx.z == 0) ? s0 : (blockIdx.z == 1) ? s1
                     : (blockIdx.z == 2) ? s2 : s3;
    __nv_bfloat16* dst = dstb + (size_t)blockIdx.z * DMODEL * DMODEL;
    __shared__ float t[32][33];
    int x = blockIdx.x * 32 + threadIdx.x;
    int y = blockIdx.y * 32 + threadIdx.y;
#pragma unroll
    for (int j = 0; j < 32; j += 8)
        t[threadIdx.y + j][threadIdx.x] = src[(size_t)(y + j) * DMODEL + x];
    __syncthreads();
    int x2 = blockIdx.y * 32 + threadIdx.x;
    int y2 = blockIdx.x * 32 + threadIdx.y;
#pragma unroll
    for (int j = 0; j < 32; j += 8)
        dst[(size_t)(y2 + j) * DMODEL + x2] = __float2bfloat16(t[threadIdx.x][threadIdx.y + j]);
}

// ---------------- bf16 GEMM: out = A[M,1024] @ Wt^T + bias --------------------
// BM=256, BN=128, BK=32. 8 warps (4m x 2n), warp tile 64x64, mma m16n8k16.
// 3-stage cp.async ring, one __syncthreads per chunk, frags via ldmatrix.
// grid.z selects (Wt, bias, out) -> fused QKV in one launch.
#define GBM 256
#define GBN 128
#define GBK 32
#define GLD 20                    // words per smem row (16 data + 4 pad)
#define GROWB (GLD*4)             // 80 bytes per row
#define G_BOFF 20480              // B half offset within stage (256 rows * 80B)
#define GSTAGE_B 30720            // (256+128) rows * 80B
#define GSMEM_B (3*GSTAGE_B)      // 92160

__global__ __launch_bounds__(256, 1) void gemm_bf16(
    const __nv_bfloat16* __restrict__ A, const __nv_bfloat16* __restrict__ Wt3,
    const float* __restrict__ b0p, const float* __restrict__ b1p,
    const float* __restrict__ b2p,
    void* __restrict__ o0p, void* __restrict__ o1p, void* __restrict__ o2p,
    int split_heads, float scale0)
{
    extern __shared__ __align__(16) uint32_t gsm[];
    const uint32_t sb = smem_u32(gsm);

    const int z = blockIdx.z;
    const __nv_bfloat16* Bt = Wt3 + (size_t)z * DMODEL * DMODEL;
    const float* bias = (z == 0) ? b0p : (z == 1) ? b1p : b2p;
    void* outp        = (z == 0) ? o0p : (z == 1) ? o1p : o2p;
    const float oscale = (z == 0) ? scale0 : 1.0f;

    const int tid  = threadIdx.x;
    const int lane = tid & 31;
    const int warp = tid >> 5;
    const int wm   = warp >> 1;          // 0..3 (64 rows each)
    const int wn   = warp & 1;           // 0..1 (64 cols each)
    const int m0   = blockIdx.y * GBM;
    const int n0   = blockIdx.x * GBN;

    const __nv_bfloat16* Abase = A  + (size_t)m0 * DMODEL;
    const __nv_bfloat16* Bbase = Bt + (size_t)n0 * DMODEL;

    // per-lane ldmatrix byte offsets
    const int lr = lane & 7;
    const uint32_t aoff = (uint32_t)((((lane >> 3) & 1) * 8 + lr) * GROWB
                                     + ((lane >> 4) & 1) * 16);
    const uint32_t boff = (uint32_t)((((lane >> 4) & 1) * 8 + lr) * GROWB
                                     + ((lane >> 3) & 1) * 16);

    float acc[4][8][4];
#pragma unroll
    for (int im = 0; im < 4; im++)
#pragma unroll
        for (int in = 0; in < 8; in++)
#pragma unroll
            for (int k = 0; k < 4; k++) acc[im][in][k] = 0.f;

#define GLOAD(c, s) do {                                                       \
        _Pragma("unroll")                                                      \
        for (int i_ = 0; i_ < 4; i_++) {          /* A: 256 rows */            \
            int idx_ = tid + i_ * 256;                                         \
            int r_ = idx_ >> 2, q_ = idx_ & 3;                                 \
            cpasync16(sb + (s) * GSTAGE_B + r_ * GROWB + q_ * 16,              \
                      Abase + (size_t)r_ * DMODEL + (c) * GBK + q_ * 8);       \
        }                                                                      \
        _Pragma("unroll")                                                      \
        for (int i_ = 0; i_ < 2; i_++) {          /* B: 128 rows */            \
            int idx_ = tid + i_ * 256;                                         \
            int r_ = idx_ >> 2, q_ = idx_ & 3;                                 \
            cpasync16(sb + (s) * GSTAGE_B + G_BOFF + r_ * GROWB + q_ * 16,     \
                      Bbase + (size_t)r_ * DMODEL + (c) * GBK + q_ * 8);       \
        }                                                                      \
        cp_commit();                                                           \
    } while (0)

    GLOAD(0, 0);
    GLOAD(1, 1);
    const int NCH = DMODEL / GBK;   // 32
    int stg = 0;
    for (int c = 0; c < NCH; c++) {
        if (c + 2 < NCH) cp_wait1(); else cp_wait0();
        __syncthreads();
        if (c + 2 < NCH) {
            int ns = stg + 2; if (ns >= 3) ns -= 3;
            GLOAD(c + 2, ns);
        }

        const uint32_t abase = sb + (uint32_t)stg * GSTAGE_B
                             + (uint32_t)(wm * 64) * GROWB + aoff;
        const uint32_t bbase = sb + (uint32_t)stg * GSTAGE_B + G_BOFF
                             + (uint32_t)(wn * 64) * GROWB + boff;

#pragma unroll
        for (int ks = 0; ks < 2; ks++) {
            uint32_t a[4][4];
#pragma unroll
            for (int im = 0; im < 4; im++)
                ldsm_x4(a[im][0], a[im][1], a[im][2], a[im][3],
                        abase + im * 16 * GROWB + ks * 32);
#pragma unroll
            for (int p = 0; p < 4; p++) {
                uint32_t b00, b01, b10, b11;
                ldsm_x4(b00, b01, b10, b11, bbase + p * 16 * GROWB + ks * 32);
#pragma unroll
                for (int im = 0; im < 4; im++) {
                    mma_bf16(acc[im][2 * p],     a[im], b00, b01);
                    mma_bf16(acc[im][2 * p + 1], a[im], b10, b11);
                }
            }
        }
        if (++stg == 3) stg = 0;
    }

    // epilogue
#pragma unroll
    for (int im = 0; im < 4; im++) {
#pragma unroll
        for (int in = 0; in < 8; in++) {
            int row = m0 + wm * 64 + im * 16 + (lane >> 2);
            int col = n0 + wn * 64 + in * 8 + 2 * (lane & 3);
            float b0 = bias[col], b1 = bias[col + 1];
            float v00 = (acc[im][in][0] + b0) * oscale;
            float v01 = (acc[im][in][1] + b1) * oscale;
            float v10 = (acc[im][in][2] + b0) * oscale;
            float v11 = (acc[im][in][3] + b1) * oscale;
            if (split_heads) {
                __nv_bfloat16* ob = (__nv_bfloat16*)outp;
                int bb = row >> 11, s = row & (SEQ - 1);
                int hh = col >> 6,  d = col & 63;
                size_t base = (((size_t)(bb * NHEAD + hh) * SEQ + s) * DHEAD + d);
                *(uint32_t*)(ob + base)              = pack_bf16(v00, v01);
                *(uint32_t*)(ob + base + 8 * DHEAD)  = pack_bf16(v10, v11);
            } else {
                float* of = (float*)outp;
                size_t base = (size_t)row * DMODEL + col;
                *(float2*)(of + base)                       = make_float2(v00, v01);
                *(float2*)(of + base + (size_t)8 * DMODEL)  = make_float2(v10, v11);
            }
        }
    }
}

// ---------------- flash attention, bf16 mma, register-resident P --------------
#define AQ 128
#define AROW 144                 // bytes per K/V smem row (128 data + 16 pad)
#define KOFF(s) ((s) * 9216)
#define VOFF(s) (18432 + (s) * 9216)
#define MOFF(s) (36864 + (s) * 256)
#define ASMEM 37376

__global__ __launch_bounds__(256, 2) void attn_kernel(
    const __nv_bfloat16* __restrict__ Q, const __nv_bfloat16* __restrict__ K,
    const __nv_bfloat16* __restrict__ V, const float* __restrict__ mask,
    __nv_bfloat16* __restrict__ ctx)
{
    __shared__ __align__(16) uint8_t smr[ASMEM];
    const uint32_t sb = smem_u32(smr);

    const int tid  = threadIdx.x;
    const int lane = tid & 31;
    const int warp = tid >> 5;

    const int q0 = blockIdx.x * AQ;
    const int h  = blockIdx.y;
    const int b  = blockIdx.z;

    const __nv_bfloat16* Qp = Q + (((size_t)(b * NHEAD + h) * SEQ + q0) * DHEAD);
    const __nv_bfloat16* Kp = K + ((size_t)(b * NHEAD + h) * SEQ) * DHEAD;
    const __nv_bfloat16* Vp = V + ((size_t)(b * NHEAD + h) * SEQ) * DHEAD;
    const float* Mp = mask + (size_t)b * SEQ;

#define APREFETCH(kt, s) do {                                                  \
        const int key0_ = (kt) * 64;                                           \
        _Pragma("unroll")                                                      \
        for (int i_ = 0; i_ < 2; i_++) {                                       \
            int idx_ = tid + i_ * 256;                                         \
            int r_ = idx_ >> 3, q_ = idx_ & 7;                                 \
            cpasync16(sb + KOFF(s) + r_ * AROW + q_ * 16,                      \
                      Kp + (size_t)(key0_ + r_) * DHEAD + q_ * 8);             \
        }                                                                      \
        _Pragma("unroll")                                                      \
        for (int i_ = 0; i_ < 2; i_++) {                                       \
            int idx_ = tid + i_ * 256;                                         \
            int r_ = idx_ >> 3, q_ = idx_ & 7;                                 \
            cpasync16(sb + VOFF(s) + r_ * AROW + q_ * 16,                      \
                      Vp + (size_t)(key0_ + r_) * DHEAD + q_ * 8);             \
        }                                                                      \
        if (tid < 16)                                                          \
            cpasync16(sb + MOFF(s) + tid * 16, Mp + key0_ + tid * 4);          \
        cp_commit();                                                           \
    } while (0)

    APREFETCH(0, 0);

    // ---- Q fragments straight from gmem (bf16 pairs are mma-native)
    uint32_t qf[4][4];
    {
        const int r = warp * 16 + (lane >> 2);
#pragma unroll
        for (int ks = 0; ks < 4; ks++) {
            int k0 = ks * 16 + 2 * (lane & 3);
            qf[ks][0] = *(const uint32_t*)(Qp + (size_t)r * DHEAD + k0);
            qf[ks][1] = *(const uint32_t*)(Qp + (size_t)(r + 8) * DHEAD + k0);
            qf[ks][2] = *(const uint32_t*)(Qp + (size_t)r * DHEAD + k0 + 8);
            qf[ks][3] = *(const uint32_t*)(Qp + (size_t)(r + 8) * DHEAD + k0 + 8);
        }
    }

    float m0 = -1e30f, m1 = -1e30f, l0 = 0.f, l1 = 0.f;
    float oacc[8][4];
#pragma unroll
    for (int in = 0; in < 8; in++)
#pragma unroll
        for (int k = 0; k < 4; k++) oacc[in][k] = 0.f;

    const int lr = lane & 7;
    const uint32_t kloff = (uint32_t)((((lane >> 4) & 1) * 8 + lr) * AROW
                                      + ((lane >> 3) & 1) * 16);
    const uint32_t vlaneoff =
        ((lane & 7) + ((lane & 8) ? 8u : 0u)) * AROW + ((lane & 16) ? 16u : 0u);

    for (int kt = 0; kt < SEQ / 64; kt++) {
        const int bsl = kt & 1;
        cp_wait0();
        __syncthreads();
        if (kt + 1 < SEQ / 64) APREFETCH(kt + 1, 1 - bsl);

        const float*   msk   = (const float*)(smr + MOFF(bsl));
        const uint32_t kbase = sb + KOFF(bsl) + kloff;
        const uint32_t vbase = sb + VOFF(bsl);

        // ---- S = Q @ K^T
        float sacc[8][4];
#pragma unroll
        for (int in = 0; in < 8; in++)
#pragma unroll
            for (int k = 0; k < 4; k++) sacc[in][k] = 0.f;

#pragma unroll
        for (int ks = 0; ks < 4; ks++) {
#pragma unroll
            for (int p = 0; p < 4; p++) {
                uint32_t b00, b01, b10, b11;
                ldsm_x4(b00, b01, b10, b11, kbase + p * (16 * AROW) + ks * 32);
                mma_bf16(sacc[2 * p],     qf[ks], b00, b01);
                mma_bf16(sacc[2 * p + 1], qf[ks], b10, b11);
            }
        }

        // ---- mask + register online softmax (base-2 domain)
        float mx0 = -1e30f, mx1 = -1e30f;
#pragma unroll
        for (int in = 0; in < 8; in++) {
            int c = in * 8 + 2 * (lane & 3);
            float mv0 = msk[c], mv1 = msk[c + 1];
            sacc[in][0] += mv0; sacc[in][1] += mv1;
            sacc[in][2] += mv0; sacc[in][3] += mv1;
            mx0 = fmaxf(mx0, fmaxf(sacc[in][0], sacc[in][1]));
            mx1 = fmaxf(mx1, fmaxf(sacc[in][2], sacc[in][3]));
        }
        mx0 = fmaxf(mx0, __shfl_xor_sync(0xffffffffu, mx0, 1));
        mx0 = fmaxf(mx0, __shfl_xor_sync(0xffffffffu, mx0, 2));
        mx1 = fmaxf(mx1, __shfl_xor_sync(0xffffffffu, mx1, 1));
        mx1 = fmaxf(mx1, __shfl_xor_sync(0xffffffffu, mx1, 2));

        const float mn0 = fmaxf(m0, mx0), mn1 = fmaxf(m1, mx1);
        const float a0 = ex2(m0 - mn0), a1 = ex2(m1 - mn1);
        m0 = mn0; m1 = mn1;

        uint32_t pk[8][2];
        float rs0 = 0.f, rs1 = 0.f;
#pragma unroll
        for (int in = 0; in < 8; in++) {
            float p0 = ex2(sacc[in][0] - mn0);
            float p1 = ex2(sacc[in][1] - mn0);
            float p2 = ex2(sacc[in][2] - mn1);
            float p3 = ex2(sacc[in][3] - mn1);
            rs0 += p0 + p1; rs1 += p2 + p3;
            pk[in][0] = pack_bf16(p0, p1);
            pk[in][1] = pack_bf16(p2, p3);
        }
        rs0 += __shfl_xor_sync(0xffffffffu, rs0, 1);
        rs0 += __shfl_xor_sync(0xffffffffu, rs0, 2);
        rs1 += __shfl_xor_sync(0xffffffffu, rs1, 1);
        rs1 += __shfl_xor_sync(0xffffffffu, rs1, 2);
        l0 = l0 * a0 + rs0;
        l1 = l1 * a1 + rs1;

#pragma unroll
        for (int in = 0; in < 8; in++) {
            oacc[in][0] *= a0; oacc[in][1] *= a0;
            oacc[in][2] *= a1; oacc[in][3] *= a1;
        }

        // ---- O += P @ V
#pragma unroll
        for (int ks = 0; ks < 4; ks++) {
            uint32_t a[4] = { pk[2 * ks][0], pk[2 * ks][1],
                              pk[2 * ks + 1][0], pk[2 * ks + 1][1] };
            uint32_t vk = vbase + (uint32_t)(ks * 16) * AROW + vlaneoff;
#pragma unroll
            for (int gi = 0; gi < 4; gi++) {
                uint32_t b0a, b1a, b0b, b1b;
                ldsm_x4_t(b0a, b1a, b0b, b1b, vk + gi * 32);
                mma_bf16(oacc[2 * gi],     a, b0a, b1a);
                mma_bf16(oacc[2 * gi + 1], a, b0b, b1b);
            }
        }
    }

    // ---- finalize: /l, write ctx bf16 [B,S,D]
    {
        const int rp = warp * 16 + (lane >> 2);
        const float il0 = 1.f / l0, il1 = 1.f / l1;
#pragma unroll
        for (int in = 0; in < 8; in++) {
            int c = in * 8 + 2 * (lane & 3);
            size_t base = ((size_t)b * SEQ + q0 + rp) * DMODEL + h * DHEAD + c;
            *(uint32_t*)(ctx + base) =
                pack_bf16(oacc[in][0] * il0, oacc[in][1] * il0);
            *(uint32_t*)(ctx + base + (size_t)8 * DMODEL) =
                pack_bf16(oacc[in][2] * il1, oacc[in][3] * il1);
        }
    }
}

// ---------------- residual + LayerNorm ---------------------------------------
__global__ __launch_bounds__(256) void ln_kernel(
    const float* __restrict__ hbuf, const float* __restrict__ x,
    const float* __restrict__ gamma, const float* __restrict__ beta,
    float* __restrict__ out)
{
    const int row = blockIdx.x;
    const int tid = threadIdx.x;
    const int lane = tid & 31, warp = tid >> 5;

    const float4* hp = (const float4*)(hbuf + (size_t)row * DMODEL);
    const float4* xp = (const float4*)(x + (size_t)row * DMODEL);
    float4 hv = hp[tid], xv = xp[tid];
    float4 y = make_float4(hv.x + xv.x, hv.y + xv.y, hv.z + xv.z, hv.w + xv.w);

    float s  = y.x + y.y + y.z + y.w;
    float sq = y.x * y.x + y.y * y.y + y.z * y.z + y.w * y.w;
#pragma unroll
    for (int o = 16; o; o >>= 1) {
        s  += __shfl_xor_sync(0xffffffffu, s, o);
        sq += __shfl_xor_sync(0xffffffffu, sq, o);
    }
    __shared__ float ss[8], ssq[8];
    if (lane == 0) { ss[warp] = s; ssq[warp] = sq; }
    __syncthreads();
    if (warp == 0) {
        s  = (lane < 8) ? ss[lane]  : 0.f;
        sq = (lane < 8) ? ssq[lane] : 0.f;
#pragma unroll
        for (int o = 4; o; o >>= 1) {
            s  += __shfl_xor_sync(0xffffffffu, s, o);
            sq += __shfl_xor_sync(0xffffffffu, sq, o);
        }
        if (lane == 0) { ss[0] = s; ssq[0] = sq; }
    }
    __syncthreads();
    s = ss[0]; sq = ssq[0];

    const float mu   = s * (1.f / DMODEL);
    const float var  = sq * (1.f / DMODEL) - mu * mu;
    const float rstd = rsqrtf(var + 1e-12f);

    float4 g = ((const float4*)gamma)[tid];
    float4 bt = ((const float4*)beta)[tid];
    float4 o;
    o.x = (y.x - mu) * rstd * g.x + bt.x;
    o.y = (y.y - mu) * rstd * g.y + bt.y;
    o.z = (y.z - mu) * rstd * g.z + bt.z;
    o.w = (y.w - mu) * rstd * g.w + bt.w;
    ((float4*)(out + (size_t)row * DMODEL))[tid] = o;
}

// ---------------- launch ------------------------------------------------------
extern "C" void kernel_launch(void* const* d_in, const int* in_sizes, int n_in,
                              void* d_out, int out_size)
{
    const float* x    = (const float*)d_in[0];
    const float* mask = (const float*)d_in[1];
    const float* Wq   = (const float*)d_in[2];
    const float* bq   = (const float*)d_in[3];
    const float* Wk   = (const float*)d_in[4];
    const float* bk   = (const float*)d_in[5];
    const float* Wv   = (const float*)d_in[6];
    const float* bv   = (const float*)d_in[7];
    const float* Wo   = (const float*)d_in[8];
    const float* bo   = (const float*)d_in[9];
    const float* gam  = (const float*)d_in[10];
    const float* bet  = (const float*)d_in[11];
    float* out = (float*)d_out;

    __nv_bfloat16 *pxb, *pQ, *pK, *pV, *pC, *pWt;
    float *pH, *pM;
    cudaGetSymbolAddress((void**)&pxb, g_xb);
    cudaGetSymbolAddress((void**)&pQ,  g_Qb);
    cudaGetSymbolAddress((void**)&pK,  g_Kb);
    cudaGetSymbolAddress((void**)&pV,  g_Vb);
    cudaGetSymbolAddress((void**)&pC,  g_ctxb);
    cudaGetSymbolAddress((void**)&pWt, g_Wtb);
    cudaGetSymbolAddress((void**)&pH,  g_h);
    cudaGetSymbolAddress((void**)&pM,  g_msc);
    __nv_bfloat16* Wto = pWt + (size_t)3 * DMODEL * DMODEL;

    cvt_kernel<<<MTOT * DMODEL / 4 / 256, 256>>>(x, (__nv_bfloat162*)pxb);
    mask_kernel<<<BATCH * SEQ / 256, 256>>>(mask, pM);
    tr_kernel<<<dim3(32, 32, 4), dim3(32, 8)>>>(Wq, Wk, Wv, Wo, pWt);

    cudaFuncSetAttribute(gemm_bf16, cudaFuncAttributeMaxDynamicSharedMemorySize, GSMEM_B);
    const float qsc = 0.125f * 1.4426950408889634f;   // fold log2e into Q

    // fused QKV: grid.z picks weight/bias/output
    gemm_bf16<<<dim3(DMODEL / GBN, MTOT / GBM, 3), 256, GSMEM_B>>>(
        pxb, pWt, bq, bk, bv, pQ, pK, pV, 1, qsc);

    attn_kernel<<<dim3(SEQ / AQ, NHEAD, BATCH), 256>>>(pQ, pK, pV, pM, pC);

    // O-projection (z=0 slot only)
    gemm_bf16<<<dim3(DMODEL / GBN, MTOT / GBM, 1), 256, GSMEM_B>>>(
        pC, Wto, bo, bo, bo, pH, pH, pH, 0, 1.0f);

    ln_kernel<<<MTOT, 256>>>(pH, x, gam, bet, out);
}

// round 10
// speedup vs baseline: 1.0904x; 1.0904x over previous
#include <cuda_runtime.h>
#include <cuda_bf16.h>
#include <cstdint>

#define BATCH 4
#define SEQ   2048
#define DMODEL 1024
#define NHEAD 16
#define DHEAD 64
#define MTOT  (BATCH*SEQ)   // 8192

// ---------------- scratch (static device globals; no runtime alloc) ----------
__device__ __nv_bfloat16 g_xb [MTOT*DMODEL];            // x in bf16
__device__ __nv_bfloat16 g_Qb [BATCH*NHEAD*SEQ*DHEAD];  // [B,H,S,DH] bf16
__device__ __nv_bfloat16 g_Kb [BATCH*NHEAD*SEQ*DHEAD];
__device__ __nv_bfloat16 g_Vb [BATCH*NHEAD*SEQ*DHEAD];
__device__ __nv_bfloat16 g_ctxb[MTOT*DMODEL];           // attention out, bf16
__device__ __nv_bfloat16 g_Wtb[4*DMODEL*DMODEL];        // transposed bf16 weights
__device__ float         g_h  [MTOT*DMODEL];            // O-proj out, fp32
__device__ float         g_msc[BATCH*SEQ];              // mask * log2(e)

// ---------------- low-level helpers ------------------------------------------
__device__ __forceinline__ uint32_t smem_u32(const void* p) {
    uint32_t a;
    asm("{ .reg .u64 t; cvta.to.shared.u64 t, %1; cvt.u32.u64 %0, t; }" : "=r"(a) : "l"(p));
    return a;
}
__device__ __forceinline__ void cpasync16(uint32_t dst, const void* src) {
    asm volatile("cp.async.cg.shared.global [%0], [%1], 16;" :: "r"(dst), "l"(src));
}
__device__ __forceinline__ void cp_commit() { asm volatile("cp.async.commit_group;"); }
__device__ __forceinline__ void cp_wait0()  { asm volatile("cp.async.wait_group 0;"); }

__device__ __forceinline__ float ex2(float x) {
    float y; asm("ex2.approx.f32 %0, %1;" : "=f"(y) : "f"(x)); return y;
}

__device__ __forceinline__ void mma_bf16(float c[4], const uint32_t a[4],
                                         uint32_t b0, uint32_t b1) {
    asm volatile(
        "mma.sync.aligned.m16n8k16.row.col.f32.bf16.bf16.f32 "
        "{%0,%1,%2,%3}, {%4,%5,%6,%7}, {%8,%9}, {%0,%1,%2,%3};"
        : "+f"(c[0]), "+f"(c[1]), "+f"(c[2]), "+f"(c[3])
        : "r"(a[0]), "r"(a[1]), "r"(a[2]), "r"(a[3]), "r"(b0), "r"(b1));
}
__device__ __forceinline__ void ldsm_x4(uint32_t& r0, uint32_t& r1,
                                        uint32_t& r2, uint32_t& r3, uint32_t addr) {
    asm volatile("ldmatrix.sync.aligned.m8n8.x4.shared.b16 {%0,%1,%2,%3}, [%4];"
        : "=r"(r0), "=r"(r1), "=r"(r2), "=r"(r3) : "r"(addr));
}
__device__ __forceinline__ void ldsm_x4_t(uint32_t& r0, uint32_t& r1,
                                          uint32_t& r2, uint32_t& r3, uint32_t addr) {
    asm volatile("ldmatrix.sync.aligned.m8n8.x4.trans.shared.b16 {%0,%1,%2,%3}, [%4];"
        : "=r"(r0), "=r"(r1), "=r"(r2), "=r"(r3) : "r"(addr));
}
__device__ __forceinline__ uint32_t pack_bf16(float lo, float hi) {
    __nv_bfloat162 t = __float22bfloat162_rn(make_float2(lo, hi));
    return *reinterpret_cast<uint32_t*>(&t);
}

// ---------------- fp32 -> bf16 convert ----------------------------------------
__global__ __launch_bounds__(256) void cvt_kernel(
    const float* __restrict__ x, __nv_bfloat162* __restrict__ o)
{
    size_t i = (size_t)blockIdx.x * 256 + threadIdx.x;   // over float4
    float4 v = ((const float4*)x)[i];
    o[2 * i]     = __float22bfloat162_rn(make_float2(v.x, v.y));
    o[2 * i + 1] = __float22bfloat162_rn(make_float2(v.z, v.w));
}

// ---------------- mask prescale: m * log2(e) ----------------------------------
__global__ __launch_bounds__(256) void mask_kernel(
    const float* __restrict__ m, float* __restrict__ o)
{
    int i = blockIdx.x * 256 + threadIdx.x;
    o[i] = m[i] * 1.4426950408889634f;
}

// -------- transpose + convert all 4 weights: W[K][N] fp32 -> Wt[N][K] bf16 ----
__global__ __launch_bounds__(256) void tr_kernel(
    const float* __restrict__ s0, const float* __restrict__ s1,
    const float* __restrict__ s2, const float* __restrict__ s3,
    __nv_bfloat16* __restrict__ dstb)
{
    const float* src = (blockIdx.z == 0) ? s0 : (blockIdx.z == 1) ? s1
                     : (blockIdx.z == 2) ? s2 : s3;
    __nv_bfloat16* dst = dstb + (size_t)blockIdx.z * DMODEL * DMODEL;
    __shared__ float t[32][33];
    int x = blockIdx.x * 32 + threadIdx.x;
    int y = blockIdx.y * 32 + threadIdx.y;
#pragma unroll
    for (int j = 0; j < 32; j += 8)
        t[threadIdx.y + j][threadIdx.x] = src[(size_t)(y + j) * DMODEL + x];
    __syncthreads();
    int x2 = blockIdx.y * 32 + threadIdx.x;
    int y2 = blockIdx.x * 32 + threadIdx.y;
#pragma unroll
    for (int j = 0; j < 32; j += 8)
        dst[(size_t)(y2 + j) * DMODEL + x2] = __float2bfloat16(t[threadIdx.x][threadIdx.y + j]);
}

// ---------------- bf16 GEMM: out = A[M,1024] @ Wt^T + bias --------------------
// R7 shape: BM=BN=128, BK=32, 8 warps (4m x 2n), warp tile 32x64, m16n8k16,
// 2-stage cp.async, static 40KB smem, 2 CTAs/SM. grid.z selects weight/bias/out
// (fused QKV in one launch; O-proj uses grid.z=1).
#define GBM 128
#define GBN 128
#define GBK 32
#define GLD 20                 // words per smem row (16 data + 4 pad)
#define GROWB (GLD*4)          // 80 bytes per row
#define GSTG (128*GLD)         // words per half-stage (A or B)

__global__ __launch_bounds__(256, 2) void gemm_bf16(
    const __nv_bfloat16* __restrict__ A, const __nv_bfloat16* __restrict__ Wt3,
    const float* __restrict__ b0p, const float* __restrict__ b1p,
    const float* __restrict__ b2p,
    void* __restrict__ o0p, void* __restrict__ o1p, void* __restrict__ o2p,
    int split_heads, float scale0)
{
    __shared__ __align__(16) uint32_t gsm[4 * GSTG];   // A0,A1,B0,B1 = 40KB
    const uint32_t sb = smem_u32(gsm);

    const int z = blockIdx.z;
    const __nv_bfloat16* Bt = Wt3 + (size_t)z * DMODEL * DMODEL;
    const float* bias = (z == 0) ? b0p : (z == 1) ? b1p : b2p;
    void* outp        = (z == 0) ? o0p : (z == 1) ? o1p : o2p;
    const float oscale = (z == 0) ? scale0 : 1.0f;

    const int tid  = threadIdx.x;
    const int lane = tid & 31;
    const int warp = tid >> 5;
    const int wm   = warp >> 1;          // 0..3
    const int wn   = warp & 1;           // 0..1
    const int m0   = blockIdx.y * GBM;
    const int n0   = blockIdx.x * GBN;

    const __nv_bfloat16* Abase = A  + (size_t)m0 * DMODEL;
    const __nv_bfloat16* Bbase = Bt + (size_t)n0 * DMODEL;

    // per-lane ldmatrix byte offsets (within a stage half)
    const int lr = lane & 7;
    const uint32_t aoff = (uint32_t)((((lane >> 3) & 1) * 8 + lr) * GROWB
                                     + ((lane >> 4) & 1) * 16);
    const uint32_t boff = (uint32_t)((((lane >> 4) & 1) * 8 + lr) * GROWB
                                     + ((lane >> 3) & 1) * 16);

    float acc[2][8][4];
#pragma unroll
    for (int im = 0; im < 2; im++)
#pragma unroll
        for (int in = 0; in < 8; in++)
#pragma unroll
            for (int k = 0; k < 4; k++) acc[im][in][k] = 0.f;

#define GLOAD(c, s) do {                                                       \
        _Pragma("unroll")                                                      \
        for (int i_ = 0; i_ < 2; i_++) {                                       \
            int idx_ = tid + i_ * 256;                                         \
            int r_ = idx_ >> 2, q_ = idx_ & 3;                                 \
            cpasync16(sb + ((s) * GSTG + r_ * GLD + q_ * 4) * 4,               \
                      Abase + (size_t)r_ * DMODEL + (c) * GBK + q_ * 8);       \
        }                                                                      \
        _Pragma("unroll")                                                      \
        for (int i_ = 0; i_ < 2; i_++) {                                       \
            int idx_ = tid + i_ * 256;                                         \
            int r_ = idx_ >> 2, q_ = idx_ & 3;                                 \
            cpasync16(sb + ((2 + (s)) * GSTG + (r_ * GLD + q_ * 4)) * 4,       \
                      Bbase + (size_t)r_ * DMODEL + (c) * GBK + q_ * 8);       \
        }                                                                      \
        cp_commit();                                                           \
    } while (0)

    GLOAD(0, 0);
    const int NCH = DMODEL / GBK;   // 32
    for (int c = 0; c < NCH; c++) {
        const int bsl = c & 1;
        cp_wait0();
        __syncthreads();
        if (c + 1 < NCH) GLOAD(c + 1, 1 - bsl);

        const uint32_t abase = sb + (uint32_t)(bsl * GSTG * 4)
                             + (uint32_t)(wm * 32) * GROWB + aoff;
        const uint32_t bbase = sb + (uint32_t)((2 + bsl) * GSTG * 4)
                             + (uint32_t)(wn * 64) * GROWB + boff;

#pragma unroll
        for (int ks = 0; ks < 2; ks++) {
            uint32_t a[2][4];
            ldsm_x4(a[0][0], a[0][1], a[0][2], a[0][3], abase + ks * 32);
            ldsm_x4(a[1][0], a[1][1], a[1][2], a[1][3], abase + 16 * GROWB + ks * 32);
#pragma unroll
            for (int p = 0; p < 4; p++) {
                uint32_t b00, b01, b10, b11;
                ldsm_x4(b00, b01, b10, b11, bbase + p * 16 * GROWB + ks * 32);
                mma_bf16(acc[0][2 * p],     a[0], b00, b01);
                mma_bf16(acc[0][2 * p + 1], a[0], b10, b11);
                mma_bf16(acc[1][2 * p],     a[1], b00, b01);
                mma_bf16(acc[1][2 * p + 1], a[1], b10, b11);
            }
        }
        __syncthreads();
    }

    // epilogue
#pragma unroll
    for (int im = 0; im < 2; im++) {
#pragma unroll
        for (int in = 0; in < 8; in++) {
            int row = m0 + wm * 32 + im * 16 + (lane >> 2);
            int col = n0 + wn * 64 + in * 8 + 2 * (lane & 3);
            float b0 = bias[col], b1 = bias[col + 1];
            float v00 = (acc[im][in][0] + b0) * oscale;
            float v01 = (acc[im][in][1] + b1) * oscale;
            float v10 = (acc[im][in][2] + b0) * oscale;
            float v11 = (acc[im][in][3] + b1) * oscale;
            if (split_heads) {
                __nv_bfloat16* ob = (__nv_bfloat16*)outp;
                int bb = row >> 11, s = row & (SEQ - 1);
                int hh = col >> 6,  d = col & 63;
                size_t base = (((size_t)(bb * NHEAD + hh) * SEQ + s) * DHEAD + d);
                *(uint32_t*)(ob + base)              = pack_bf16(v00, v01);
                *(uint32_t*)(ob + base + 8 * DHEAD)  = pack_bf16(v10, v11);
            } else {
                float* of = (float*)outp;
                size_t base = (size_t)row * DMODEL + col;
                *(float2*)(of + base)                       = make_float2(v00, v01);
                *(float2*)(of + base + (size_t)8 * DMODEL)  = make_float2(v10, v11);
            }
        }
    }
}

// ---------------- flash attention, bf16 mma, register-resident P --------------
// CTA: (b,h,128-query tile), 8 warps x 16 rows, full 64-key width per warp.
// Base-2 softmax (Q pre-scaled by 0.125*log2e, mask by log2e), ex2.approx.
// K frags via ldmatrix.x4, V via x4.trans, cp.async double-buffered.
#define AQ 128
#define AROW 144                 // bytes per K/V smem row (128 data + 16 pad)
#define KOFF(s) ((s) * 9216)
#define VOFF(s) (18432 + (s) * 9216)
#define MOFF(s) (36864 + (s) * 256)
#define ASMEM 37376

__global__ __launch_bounds__(256, 2) void attn_kernel(
    const __nv_bfloat16* __restrict__ Q, const __nv_bfloat16* __restrict__ K,
    const __nv_bfloat16* __restrict__ V, const float* __restrict__ mask,
    __nv_bfloat16* __restrict__ ctx)
{
    __shared__ __align__(16) uint8_t smr[ASMEM];
    const uint32_t sb = smem_u32(smr);

    const int tid  = threadIdx.x;
    const int lane = tid & 31;
    const int warp = tid >> 5;

    const int q0 = blockIdx.x * AQ;
    const int h  = blockIdx.y;
    const int b  = blockIdx.z;

    const __nv_bfloat16* Qp = Q + (((size_t)(b * NHEAD + h) * SEQ + q0) * DHEAD);
    const __nv_bfloat16* Kp = K + ((size_t)(b * NHEAD + h) * SEQ) * DHEAD;
    const __nv_bfloat16* Vp = V + ((size_t)(b * NHEAD + h) * SEQ) * DHEAD;
    const float* Mp = mask + (size_t)b * SEQ;

#define APREFETCH(kt, s) do {                                                  \
        const int key0_ = (kt) * 64;                                           \
        _Pragma("unroll")                                                      \
        for (int i_ = 0; i_ < 2; i_++) {                                       \
            int idx_ = tid + i_ * 256;                                         \
            int r_ = idx_ >> 3, q_ = idx_ & 7;                                 \
            cpasync16(sb + KOFF(s) + r_ * AROW + q_ * 16,                      \
                      Kp + (size_t)(key0_ + r_) * DHEAD + q_ * 8);             \
        }                                                                      \
        _Pragma("unroll")                                                      \
        for (int i_ = 0; i_ < 2; i_++) {                                       \
            int idx_ = tid + i_ * 256;                                         \
            int r_ = idx_ >> 3, q_ = idx_ & 7;                                 \
            cpasync16(sb + VOFF(s) + r_ * AROW + q_ * 16,                      \
                      Vp + (size_t)(key0_ + r_) * DHEAD + q_ * 8);             \
        }                                                                      \
        if (tid < 16)                                                          \
            cpasync16(sb + MOFF(s) + tid * 16, Mp + key0_ + tid * 4);          \
        cp_commit();                                                           \
    } while (0)

    APREFETCH(0, 0);

    // ---- Q fragments straight from gmem (bf16 pairs are mma-native)
    uint32_t qf[4][4];
    {
        const int r = warp * 16 + (lane >> 2);
#pragma unroll
        for (int ks = 0; ks < 4; ks++) {
            int k0 = ks * 16 + 2 * (lane & 3);
            qf[ks][0] = *(const uint32_t*)(Qp + (size_t)r * DHEAD + k0);
            qf[ks][1] = *(const uint32_t*)(Qp + (size_t)(r + 8) * DHEAD + k0);
            qf[ks][2] = *(const uint32_t*)(Qp + (size_t)r * DHEAD + k0 + 8);
            qf[ks][3] = *(const uint32_t*)(Qp + (size_t)(r + 8) * DHEAD + k0 + 8);
        }
    }

    float m0 = -1e30f, m1 = -1e30f, l0 = 0.f, l1 = 0.f;
    float oacc[8][4];
#pragma unroll
    for (int in = 0; in < 8; in++)
#pragma unroll
        for (int k = 0; k < 4; k++) oacc[in][k] = 0.f;

    const int lr = lane & 7;
    const uint32_t kloff = (uint32_t)((((lane >> 4) & 1) * 8 + lr) * AROW
                                      + ((lane >> 3) & 1) * 16);
    const uint32_t vlaneoff =
        ((lane & 7) + ((lane & 8) ? 8u : 0u)) * AROW + ((lane & 16) ? 16u : 0u);

    for (int kt = 0; kt < SEQ / 64; kt++) {
        const int bsl = kt & 1;
        cp_wait0();
        __syncthreads();
        if (kt + 1 < SEQ / 64) APREFETCH(kt + 1, 1 - bsl);

        const float*   msk   = (const float*)(smr + MOFF(bsl));
        const uint32_t kbase = sb + KOFF(bsl) + kloff;
        const uint32_t vbase = sb + VOFF(bsl);

        // ---- S = Q @ K^T
        float sacc[8][4];
#pragma unroll
        for (int in = 0; in < 8; in++)
#pragma unroll
            for (int k = 0; k < 4; k++) sacc[in][k] = 0.f;

#pragma unroll
        for (int ks = 0; ks < 4; ks++) {
#pragma unroll
            for (int p = 0; p < 4; p++) {
                uint32_t b00, b01, b10, b11;
                ldsm_x4(b00, b01, b10, b11, kbase + p * (16 * AROW) + ks * 32);
                mma_bf16(sacc[2 * p],     qf[ks], b00, b01);
                mma_bf16(sacc[2 * p + 1], qf[ks], b10, b11);
            }
        }

        // ---- mask + register online softmax (base-2 domain)
        float mx0 = -1e30f, mx1 = -1e30f;
#pragma unroll
        for (int in = 0; in < 8; in++) {
            int c = in * 8 + 2 * (lane & 3);
            float mv0 = msk[c], mv1 = msk[c + 1];
            sacc[in][0] += mv0; sacc[in][1] += mv1;
            sacc[in][2] += mv0; sacc[in][3] += mv1;
            mx0 = fmaxf(mx0, fmaxf(sacc[in][0], sacc[in][1]));
            mx1 = fmaxf(mx1, fmaxf(sacc[in][2], sacc[in][3]));
        }
        mx0 = fmaxf(mx0, __shfl_xor_sync(0xffffffffu, mx0, 1));
        mx0 = fmaxf(mx0, __shfl_xor_sync(0xffffffffu, mx0, 2));
        mx1 = fmaxf(mx1, __shfl_xor_sync(0xffffffffu, mx1, 1));
        mx1 = fmaxf(mx1, __shfl_xor_sync(0xffffffffu, mx1, 2));

        const float mn0 = fmaxf(m0, mx0), mn1 = fmaxf(m1, mx1);
        const float a0 = ex2(m0 - mn0), a1 = ex2(m1 - mn1);
        m0 = mn0; m1 = mn1;

        uint32_t pk[8][2];
        float rs0 = 0.f, rs1 = 0.f;
#pragma unroll
        for (int in = 0; in < 8; in++) {
            float p0 = ex2(sacc[in][0] - mn0);
            float p1 = ex2(sacc[in][1] - mn0);
            float p2 = ex2(sacc[in][2] - mn1);
            float p3 = ex2(sacc[in][3] - mn1);
            rs0 += p0 + p1; rs1 += p2 + p3;
            pk[in][0] = pack_bf16(p0, p1);
            pk[in][1] = pack_bf16(p2, p3);
        }
        rs0 += __shfl_xor_sync(0xffffffffu, rs0, 1);
        rs0 += __shfl_xor_sync(0xffffffffu, rs0, 2);
        rs1 += __shfl_xor_sync(0xffffffffu, rs1, 1);
        rs1 += __shfl_xor_sync(0xffffffffu, rs1, 2);
        l0 = l0 * a0 + rs0;
        l1 = l1 * a1 + rs1;

#pragma unroll
        for (int in = 0; in < 8; in++) {
            oacc[in][0] *= a0; oacc[in][1] *= a0;
            oacc[in][2] *= a1; oacc[in][3] *= a1;
        }

        // ---- O += P @ V
#pragma unroll
        for (int ks = 0; ks < 4; ks++) {
            uint32_t a[4] = { pk[2 * ks][0], pk[2 * ks][1],
                              pk[2 * ks + 1][0], pk[2 * ks + 1][1] };
            uint32_t vk = vbase + (uint32_t)(ks * 16) * AROW + vlaneoff;
#pragma unroll
            for (int gi = 0; gi < 4; gi++) {
                uint32_t b0a, b1a, b0b, b1b;
                ldsm_x4_t(b0a, b1a, b0b, b1b, vk + gi * 32);
                mma_bf16(oacc[2 * gi],     a, b0a, b1a);
                mma_bf16(oacc[2 * gi + 1], a, b0b, b1b);
            }
        }
    }

    // ---- finalize: /l, write ctx bf16 [B,S,D]
    {
        const int rp = warp * 16 + (lane >> 2);
        const float il0 = 1.f / l0, il1 = 1.f / l1;
#pragma unroll
        for (int in = 0; in < 8; in++) {
            int c = in * 8 + 2 * (lane & 3);
            size_t base = ((size_t)b * SEQ + q0 + rp) * DMODEL + h * DHEAD + c;
            *(uint32_t*)(ctx + base) =
                pack_bf16(oacc[in][0] * il0, oacc[in][1] * il0);
            *(uint32_t*)(ctx + base + (size_t)8 * DMODEL) =
                pack_bf16(oacc[in][2] * il1, oacc[in][3] * il1);
        }
    }
}

// ---------------- residual + LayerNorm ---------------------------------------
__global__ __launch_bounds__(256) void ln_kernel(
    const float* __restrict__ hbuf, const float* __restrict__ x,
    const float* __restrict__ gamma, const float* __restrict__ beta,
    float* __restrict__ out)
{
    const int row = blockIdx.x;
    const int tid = threadIdx.x;
    const int lane = tid & 31, warp = tid >> 5;

    const float4* hp = (const float4*)(hbuf + (size_t)row * DMODEL);
    const float4* xp = (const float4*)(x + (size_t)row * DMODEL);
    float4 hv = hp[tid], xv = xp[tid];
    float4 y = make_float4(hv.x + xv.x, hv.y + xv.y, hv.z + xv.z, hv.w + xv.w);

    float s  = y.x + y.y + y.z + y.w;
    float sq = y.x * y.x + y.y * y.y + y.z * y.z + y.w * y.w;
#pragma unroll
    for (int o = 16; o; o >>= 1) {
        s  += __shfl_xor_sync(0xffffffffu, s, o);
        sq += __shfl_xor_sync(0xffffffffu, sq, o);
    }
    __shared__ float ss[8], ssq[8];
    if (lane == 0) { ss[warp] = s; ssq[warp] = sq; }
    __syncthreads();
    if (warp == 0) {
        s  = (lane < 8) ? ss[lane]  : 0.f;
        sq = (lane < 8) ? ssq[lane] : 0.f;
#pragma unroll
        for (int o = 4; o; o >>= 1) {
            s  += __shfl_xor_sync(0xffffffffu, s, o);
            sq += __shfl_xor_sync(0xffffffffu, sq, o);
        }
        if (lane == 0) { ss[0] = s; ssq[0] = sq; }
    }
    __syncthreads();
    s = ss[0]; sq = ssq[0];

    const float mu   = s * (1.f / DMODEL);
    const float var  = sq * (1.f / DMODEL) - mu * mu;
    const float rstd = rsqrtf(var + 1e-12f);

    float4 g = ((const float4*)gamma)[tid];
    float4 bt = ((const float4*)beta)[tid];
    float4 o;
    o.x = (y.x - mu) * rstd * g.x + bt.x;
    o.y = (y.y - mu) * rstd * g.y + bt.y;
    o.z = (y.z - mu) * rstd * g.z + bt.z;
    o.w = (y.w - mu) * rstd * g.w + bt.w;
    ((float4*)(out + (size_t)row * DMODEL))[tid] = o;
}

// ---------------- launch ------------------------------------------------------
extern "C" void kernel_launch(void* const* d_in, const int* in_sizes, int n_in,
                              void* d_out, int out_size)
{
    const float* x    = (const float*)d_in[0];
    const float* mask = (const float*)d_in[1];
    const float* Wq   = (const float*)d_in[2];
    const float* bq   = (const float*)d_in[3];
    const float* Wk   = (const float*)d_in[4];
    const float* bk   = (const float*)d_in[5];
    const float* Wv   = (const float*)d_in[6];
    const float* bv   = (const float*)d_in[7];
    const float* Wo   = (const float*)d_in[8];
    const float* bo   = (const float*)d_in[9];
    const float* gam  = (const float*)d_in[10];
    const float* bet  = (const float*)d_in[11];
    float* out = (float*)d_out;

    __nv_bfloat16 *pxb, *pQ, *pK, *pV, *pC, *pWt;
    float *pH, *pM;
    cudaGetSymbolAddress((void**)&pxb, g_xb);
    cudaGetSymbolAddress((void**)&pQ,  g_Qb);
    cudaGetSymbolAddress((void**)&pK,  g_Kb);
    cudaGetSymbolAddress((void**)&pV,  g_Vb);
    cudaGetSymbolAddress((void**)&pC,  g_ctxb);
    cudaGetSymbolAddress((void**)&pWt, g_Wtb);
    cudaGetSymbolAddress((void**)&pH,  g_h);
    cudaGetSymbolAddress((void**)&pM,  g_msc);
    __nv_bfloat16* Wto = pWt + (size_t)3 * DMODEL * DMODEL;

    cvt_kernel<<<MTOT * DMODEL / 4 / 256, 256>>>(x, (__nv_bfloat162*)pxb);
    mask_kernel<<<BATCH * SEQ / 256, 256>>>(mask, pM);
    tr_kernel<<<dim3(32, 32, 4), dim3(32, 8)>>>(Wq, Wk, Wv, Wo, pWt);

    const float qsc = 0.125f * 1.4426950408889634f;   // fold log2e into Q

    // fused QKV: grid.z picks weight/bias/output (R7 tile shape, 2 CTAs/SM)
    gemm_bf16<<<dim3(DMODEL / GBN, MTOT / GBM, 3), 256>>>(
        pxb, pWt, bq, bk, bv, pQ, pK, pV, 1, qsc);

    attn_kernel<<<dim3(SEQ / AQ, NHEAD, BATCH), 256>>>(pQ, pK, pV, pM, pC);

    // O-projection (grid.z=1, weight slot 0 = Wto)
    gemm_bf16<<<dim3(DMODEL / GBN, MTOT / GBM, 1), 256>>>(
        pC, Wto, bo, bo, bo, pH, pH, pH, 0, 1.0f);

    ln_kernel<<<MTOT, 256>>>(pH, x, gam, bet, out);
}

// round 11
// speedup vs baseline: 1.2173x; 1.1163x over previous
#include <cuda_runtime.h>
#include <cuda_bf16.h>
#include <cuda_fp16.h>
#include <cstdint>

#define BATCH 4
#define SEQ   2048
#define DMODEL 1024
#define NHEAD 16
#define DHEAD 64
#define MTOT  (BATCH*SEQ)   // 8192

// ---------------- scratch (static device globals; no runtime alloc) ----------
__device__ __nv_bfloat16 g_xb [MTOT*DMODEL];            // x in bf16
__device__ __nv_bfloat16 g_Qb [BATCH*NHEAD*SEQ*DHEAD];  // [B,H,S,DH] bf16
__device__ __nv_bfloat16 g_Kb [BATCH*NHEAD*SEQ*DHEAD];  // bf16
__device__ __half        g_Vh [BATCH*NHEAD*SEQ*DHEAD];  // fp16 (for f16 PV mma)
__device__ __nv_bfloat16 g_ctxb[MTOT*DMODEL];           // attention out, bf16
__device__ __nv_bfloat16 g_Wtb[4*DMODEL*DMODEL];        // transposed bf16 weights
__device__ float         g_h  [MTOT*DMODEL];            // O-proj out, fp32
__device__ float         g_msc[BATCH*SEQ];              // mask * log2(e)

// ---------------- low-level helpers ------------------------------------------
__device__ __forceinline__ uint32_t smem_u32(const void* p) {
    uint32_t a;
    asm("{ .reg .u64 t; cvta.to.shared.u64 t, %1; cvt.u32.u64 %0, t; }" : "=r"(a) : "l"(p));
    return a;
}
__device__ __forceinline__ void cpasync16(uint32_t dst, const void* src) {
    asm volatile("cp.async.cg.shared.global [%0], [%1], 16;" :: "r"(dst), "l"(src));
}
__device__ __forceinline__ void cp_commit() { asm volatile("cp.async.commit_group;"); }
__device__ __forceinline__ void cp_wait0()  { asm volatile("cp.async.wait_group 0;"); }

// pack two f32 -> f16x2 (lo in low half), then exp2 both halves in ONE MUFU op
__device__ __forceinline__ uint32_t ex2_f16x2(float lo, float hi) {
    uint32_t d;
    asm("cvt.rn.f16x2.f32 %0, %1, %2;" : "=r"(d) : "f"(hi), "f"(lo));
    asm("ex2.approx.f16x2 %0, %0;" : "+r"(d));
    return d;
}

__device__ __forceinline__ void mma_bf16(float c[4], const uint32_t a[4],
                                         uint32_t b0, uint32_t b1) {
    asm volatile(
        "mma.sync.aligned.m16n8k16.row.col.f32.bf16.bf16.f32 "
        "{%0,%1,%2,%3}, {%4,%5,%6,%7}, {%8,%9}, {%0,%1,%2,%3};"
        : "+f"(c[0]), "+f"(c[1]), "+f"(c[2]), "+f"(c[3])
        : "r"(a[0]), "r"(a[1]), "r"(a[2]), "r"(a[3]), "r"(b0), "r"(b1));
}
__device__ __forceinline__ void mma_f16(float c[4], const uint32_t a[4],
                                        uint32_t b0, uint32_t b1) {
    asm volatile(
        "mma.sync.aligned.m16n8k16.row.col.f32.f16.f16.f32 "
        "{%0,%1,%2,%3}, {%4,%5,%6,%7}, {%8,%9}, {%0,%1,%2,%3};"
        : "+f"(c[0]), "+f"(c[1]), "+f"(c[2]), "+f"(c[3])
        : "r"(a[0]), "r"(a[1]), "r"(a[2]), "r"(a[3]), "r"(b0), "r"(b1));
}
__device__ __forceinline__ void ldsm_x4(uint32_t& r0, uint32_t& r1,
                                        uint32_t& r2, uint32_t& r3, uint32_t addr) {
    asm volatile("ldmatrix.sync.aligned.m8n8.x4.shared.b16 {%0,%1,%2,%3}, [%4];"
        : "=r"(r0), "=r"(r1), "=r"(r2), "=r"(r3) : "r"(addr));
}
__device__ __forceinline__ void ldsm_x4_t(uint32_t& r0, uint32_t& r1,
                                          uint32_t& r2, uint32_t& r3, uint32_t addr) {
    asm volatile("ldmatrix.sync.aligned.m8n8.x4.trans.shared.b16 {%0,%1,%2,%3}, [%4];"
        : "=r"(r0), "=r"(r1), "=r"(r2), "=r"(r3) : "r"(addr));
}
__device__ __forceinline__ uint32_t pack_bf16(float lo, float hi) {
    __nv_bfloat162 t = __float22bfloat162_rn(make_float2(lo, hi));
    return *reinterpret_cast<uint32_t*>(&t);
}
__device__ __forceinline__ uint32_t pack_f16(float lo, float hi) {
    __half2 t = __floats2half2_rn(lo, hi);
    return *reinterpret_cast<uint32_t*>(&t);
}

// ---------------- fp32 -> bf16 convert ----------------------------------------
__global__ __launch_bounds__(256) void cvt_kernel(
    const float* __restrict__ x, __nv_bfloat162* __restrict__ o)
{
    size_t i = (size_t)blockIdx.x * 256 + threadIdx.x;   // over float4
    float4 v = ((const float4*)x)[i];
    o[2 * i]     = __float22bfloat162_rn(make_float2(v.x, v.y));
    o[2 * i + 1] = __float22bfloat162_rn(make_float2(v.z, v.w));
}

// ---------------- mask prescale: m * log2(e) ----------------------------------
__global__ __launch_bounds__(256) void mask_kernel(
    const float* __restrict__ m, float* __restrict__ o)
{
    int i = blockIdx.x * 256 + threadIdx.x;
    o[i] = m[i] * 1.4426950408889634f;
}

// -------- transpose + convert all 4 weights: W[K][N] fp32 -> Wt[N][K] bf16 ----
__global__ __launch_bounds__(256) void tr_kernel(
    const float* __restrict__ s0, const float* __restrict__ s1,
    const float* __restrict__ s2, const float* __restrict__ s3,
    __nv_bfloat16* __restrict__ dstb)
{
    const float* src = (blockIdx.z == 0) ? s0 : (blockIdx.z == 1) ? s1
                     : (blockIdx.z == 2) ? s2 : s3;
    __nv_bfloat16* dst = dstb + (size_t)blockIdx.z * DMODEL * DMODEL;
    __shared__ float t[32][33];
    int x = blockIdx.x * 32 + threadIdx.x;
    int y = blockIdx.y * 32 + threadIdx.y;
#pragma unroll
    for (int j = 0; j < 32; j += 8)
        t[threadIdx.y + j][threadIdx.x] = src[(size_t)(y + j) * DMODEL + x];
    __syncthreads();
    int x2 = blockIdx.y * 32 + threadIdx.x;
    int y2 = blockIdx.x * 32 + threadIdx.y;
#pragma unroll
    for (int j = 0; j < 32; j += 8)
        dst[(size_t)(y2 + j) * DMODEL + x2] = __float2bfloat16(t[threadIdx.x][threadIdx.y + j]);
}

// ---------------- bf16 GEMM: out = A[M,1024] @ Wt^T + bias --------------------
// R7 shape: BM=BN=128, BK=32, 8 warps (4m x 2n), warp tile 32x64, m16n8k16,
// 2-stage cp.async, static 40KB smem, 2 CTAs/SM. grid.z selects weight/bias/out.
// z==2 (V projection) emits fp16; other split_heads outputs emit bf16.
#define GBM 128
#define GBN 128
#define GBK 32
#define GLD 20                 // words per smem row (16 data + 4 pad)
#define GROWB (GLD*4)          // 80 bytes per row
#define GSTG (128*GLD)         // words per half-stage (A or B)

__global__ __launch_bounds__(256, 2) void gemm_bf16(
    const __nv_bfloat16* __restrict__ A, const __nv_bfloat16* __restrict__ Wt3,
    const float* __restrict__ b0p, const float* __restrict__ b1p,
    const float* __restrict__ b2p,
    void* __restrict__ o0p, void* __restrict__ o1p, void* __restrict__ o2p,
    int split_heads, float scale0)
{
    __shared__ __align__(16) uint32_t gsm[4 * GSTG];   // A0,A1,B0,B1 = 40KB
    const uint32_t sb = smem_u32(gsm);

    const int z = blockIdx.z;
    const __nv_bfloat16* Bt = Wt3 + (size_t)z * DMODEL * DMODEL;
    const float* bias = (z == 0) ? b0p : (z == 1) ? b1p : b2p;
    void* outp        = (z == 0) ? o0p : (z == 1) ? o1p : o2p;
    const float oscale = (z == 0) ? scale0 : 1.0f;
    const int fp16out  = (z == 2);

    const int tid  = threadIdx.x;
    const int lane = tid & 31;
    const int warp = tid >> 5;
    const int wm   = warp >> 1;          // 0..3
    const int wn   = warp & 1;           // 0..1
    const int m0   = blockIdx.y * GBM;
    const int n0   = blockIdx.x * GBN;

    const __nv_bfloat16* Abase = A  + (size_t)m0 * DMODEL;
    const __nv_bfloat16* Bbase = Bt + (size_t)n0 * DMODEL;

    const int lr = lane & 7;
    const uint32_t aoff = (uint32_t)((((lane >> 3) & 1) * 8 + lr) * GROWB
                                     + ((lane >> 4) & 1) * 16);
    const uint32_t boff = (uint32_t)((((lane >> 4) & 1) * 8 + lr) * GROWB
                                     + ((lane >> 3) & 1) * 16);

    float acc[2][8][4];
#pragma unroll
    for (int im = 0; im < 2; im++)
#pragma unroll
        for (int in = 0; in < 8; in++)
#pragma unroll
            for (int k = 0; k < 4; k++) acc[im][in][k] = 0.f;

#define GLOAD(c, s) do {                                                       \
        _Pragma("unroll")                                                      \
        for (int i_ = 0; i_ < 2; i_++) {                                       \
            int idx_ = tid + i_ * 256;                                         \
            int r_ = idx_ >> 2, q_ = idx_ & 3;                                 \
            cpasync16(sb + ((s) * GSTG + r_ * GLD + q_ * 4) * 4,               \
                      Abase + (size_t)r_ * DMODEL + (c) * GBK + q_ * 8);       \
        }                                                                      \
        _Pragma("unroll")                                                      \
        for (int i_ = 0; i_ < 2; i_++) {                                       \
            int idx_ = tid + i_ * 256;                                         \
            int r_ = idx_ >> 2, q_ = idx_ & 3;                                 \
            cpasync16(sb + ((2 + (s)) * GSTG + (r_ * GLD + q_ * 4)) * 4,       \
                      Bbase + (size_t)r_ * DMODEL + (c) * GBK + q_ * 8);       \
        }                                                                      \
        cp_commit();                                                           \
    } while (0)

    GLOAD(0, 0);
    const int NCH = DMODEL / GBK;   // 32
    for (int c = 0; c < NCH; c++) {
        const int bsl = c & 1;
        cp_wait0();
        __syncthreads();
        if (c + 1 < NCH) GLOAD(c + 1, 1 - bsl);

        const uint32_t abase = sb + (uint32_t)(bsl * GSTG * 4)
                             + (uint32_t)(wm * 32) * GROWB + aoff;
        const uint32_t bbase = sb + (uint32_t)((2 + bsl) * GSTG * 4)
                             + (uint32_t)(wn * 64) * GROWB + boff;

#pragma unroll
        for (int ks = 0; ks < 2; ks++) {
            uint32_t a[2][4];
            ldsm_x4(a[0][0], a[0][1], a[0][2], a[0][3], abase + ks * 32);
            ldsm_x4(a[1][0], a[1][1], a[1][2], a[1][3], abase + 16 * GROWB + ks * 32);
#pragma unroll
            for (int p = 0; p < 4; p++) {
                uint32_t b00, b01, b10, b11;
                ldsm_x4(b00, b01, b10, b11, bbase + p * 16 * GROWB + ks * 32);
                mma_bf16(acc[0][2 * p],     a[0], b00, b01);
                mma_bf16(acc[0][2 * p + 1], a[0], b10, b11);
                mma_bf16(acc[1][2 * p],     a[1], b00, b01);
                mma_bf16(acc[1][2 * p + 1], a[1], b10, b11);
            }
        }
        __syncthreads();
    }

    // epilogue
#pragma unroll
    for (int im = 0; im < 2; im++) {
#pragma unroll
        for (int in = 0; in < 8; in++) {
            int row = m0 + wm * 32 + im * 16 + (lane >> 2);
            int col = n0 + wn * 64 + in * 8 + 2 * (lane & 3);
            float b0 = bias[col], b1 = bias[col + 1];
            float v00 = (acc[im][in][0] + b0) * oscale;
            float v01 = (acc[im][in][1] + b1) * oscale;
            float v10 = (acc[im][in][2] + b0) * oscale;
            float v11 = (acc[im][in][3] + b1) * oscale;
            if (split_heads) {
                uint16_t* ob = (uint16_t*)outp;
                int bb = row >> 11, s = row & (SEQ - 1);
                int hh = col >> 6,  d = col & 63;
                size_t base = (((size_t)(bb * NHEAD + hh) * SEQ + s) * DHEAD + d);
                uint32_t p0 = fp16out ? pack_f16(v00, v01) : pack_bf16(v00, v01);
                uint32_t p1 = fp16out ? pack_f16(v10, v11) : pack_bf16(v10, v11);
                *(uint32_t*)(ob + base)              = p0;
                *(uint32_t*)(ob + base + 8 * DHEAD)  = p1;
            } else {
                float* of = (float*)outp;
                size_t base = (size_t)row * DMODEL + col;
                *(float2*)(of + base)                       = make_float2(v00, v01);
                *(float2*)(of + base + (size_t)8 * DMODEL)  = make_float2(v10, v11);
            }
        }
    }
}

// ---------------- flash attention ---------------------------------------------
// CTA: (b,h,128-query tile), 8 warps x 16 rows, full 64-key width per warp.
// No-max base-2 softmax (scores bounded): p = ex2.f16x2(s+mask). P is fp16,
// V is fp16, PV mma f16. Row-sum l accumulated by an extra mma against a
// CONSTANT all-ones B fragment (0x3C003C00) -> no shfl, no scalar sums.
#define AQ 128
#define AROW 144                 // bytes per K/V smem row (128 data + 16 pad)
#define KOFF(s) ((s) * 9216)
#define VOFF(s) (18432 + (s) * 9216)
#define MOFF(s) (36864 + (s) * 256)
#define ASMEM 37376
#define ONE2 0x3C003C00u         // fp16x2 (1.0, 1.0)

__global__ __launch_bounds__(256, 2) void attn_kernel(
    const __nv_bfloat16* __restrict__ Q, const __nv_bfloat16* __restrict__ K,
    const __half* __restrict__ V, const float* __restrict__ mask,
    __nv_bfloat16* __restrict__ ctx)
{
    __shared__ __align__(16) uint8_t smr[ASMEM];
    const uint32_t sb = smem_u32(smr);

    const int tid  = threadIdx.x;
    const int lane = tid & 31;
    const int warp = tid >> 5;

    const int q0 = blockIdx.x * AQ;
    const int h  = blockIdx.y;
    const int b  = blockIdx.z;

    const __nv_bfloat16* Qp = Q + (((size_t)(b * NHEAD + h) * SEQ + q0) * DHEAD);
    const __nv_bfloat16* Kp = K + ((size_t)(b * NHEAD + h) * SEQ) * DHEAD;
    const __half*        Vp = V + ((size_t)(b * NHEAD + h) * SEQ) * DHEAD;
    const float* Mp = mask + (size_t)b * SEQ;

#define APREFETCH(kt, s) do {                                                  \
        const int key0_ = (kt) * 64;                                           \
        _Pragma("unroll")                                                      \
        for (int i_ = 0; i_ < 2; i_++) {                                       \
            int idx_ = tid + i_ * 256;                                         \
            int r_ = idx_ >> 3, q_ = idx_ & 7;                                 \
            cpasync16(sb + KOFF(s) + r_ * AROW + q_ * 16,                      \
                      Kp + (size_t)(key0_ + r_) * DHEAD + q_ * 8);             \
        }                                                                      \
        _Pragma("unroll")                                                      \
        for (int i_ = 0; i_ < 2; i_++) {                                       \
            int idx_ = tid + i_ * 256;                                         \
            int r_ = idx_ >> 3, q_ = idx_ & 7;                                 \
            cpasync16(sb + VOFF(s) + r_ * AROW + q_ * 16,                      \
                      Vp + (size_t)(key0_ + r_) * DHEAD + q_ * 8);             \
        }                                                                      \
        if (tid < 16)                                                          \
            cpasync16(sb + MOFF(s) + tid * 16, Mp + key0_ + tid * 4);          \
        cp_commit();                                                           \
    } while (0)

    APREFETCH(0, 0);

    // ---- Q fragments straight from gmem (bf16 pairs are mma-native)
    uint32_t qf[4][4];
    {
        const int r = warp * 16 + (lane >> 2);
#pragma unroll
        for (int ks = 0; ks < 4; ks++) {
            int k0 = ks * 16 + 2 * (lane & 3);
            qf[ks][0] = *(const uint32_t*)(Qp + (size_t)r * DHEAD + k0);
            qf[ks][1] = *(const uint32_t*)(Qp + (size_t)(r + 8) * DHEAD + k0);
            qf[ks][2] = *(const uint32_t*)(Qp + (size_t)r * DHEAD + k0 + 8);
            qf[ks][3] = *(const uint32_t*)(Qp + (size_t)(r + 8) * DHEAD + k0 + 8);
        }
    }

    float oacc[8][4];
#pragma unroll
    for (int in = 0; in < 8; in++)
#pragma unroll
        for (int k = 0; k < 4; k++) oacc[in][k] = 0.f;
    float lacc[4] = {0.f, 0.f, 0.f, 0.f};   // row-sum accumulator (ones-mma)

    const int lr = lane & 7;
    const uint32_t kloff = (uint32_t)((((lane >> 4) & 1) * 8 + lr) * AROW
                                      + ((lane >> 3) & 1) * 16);
    const uint32_t vlaneoff =
        ((lane & 7) + ((lane & 8) ? 8u : 0u)) * AROW + ((lane & 16) ? 16u : 0u);

    for (int kt = 0; kt < SEQ / 64; kt++) {
        const int bsl = kt & 1;
        cp_wait0();
        __syncthreads();
        if (kt + 1 < SEQ / 64) APREFETCH(kt + 1, 1 - bsl);

        const float*   msk   = (const float*)(smr + MOFF(bsl));
        const uint32_t kbase = sb + KOFF(bsl) + kloff;
        const uint32_t vbase = sb + VOFF(bsl);

        // ---- S = Q @ K^T  (bf16 mma)
        float sacc[8][4];
#pragma unroll
        for (int in = 0; in < 8; in++)
#pragma unroll
            for (int k = 0; k < 4; k++) sacc[in][k] = 0.f;

#pragma unroll
        for (int ks = 0; ks < 4; ks++) {
#pragma unroll
            for (int p = 0; p < 4; p++) {
                uint32_t b00, b01, b10, b11;
                ldsm_x4(b00, b01, b10, b11, kbase + p * (16 * AROW) + ks * 32);
                mma_bf16(sacc[2 * p],     qf[ks], b00, b01);
                mma_bf16(sacc[2 * p + 1], qf[ks], b10, b11);
            }
        }

        // ---- mask + no-max base-2 softmax -> fp16 P (one MUFU per pair)
        uint32_t pk[8][2];
#pragma unroll
        for (int in = 0; in < 8; in++) {
            int c = in * 8 + 2 * (lane & 3);
            float mv0 = msk[c], mv1 = msk[c + 1];
            pk[in][0] = ex2_f16x2(sacc[in][0] + mv0, sacc[in][1] + mv1);
            pk[in][1] = ex2_f16x2(sacc[in][2] + mv0, sacc[in][3] + mv1);
        }

        // ---- O += P @ V (f16 mma); l += P @ ones (constant B fragment)
#pragma unroll
        for (int ks = 0; ks < 4; ks++) {
            uint32_t a[4] = { pk[2 * ks][0], pk[2 * ks][1],
                              pk[2 * ks + 1][0], pk[2 * ks + 1][1] };
            mma_f16(lacc, a, ONE2, ONE2);
            uint32_t vk = vbase + (uint32_t)(ks * 16) * AROW + vlaneoff;
#pragma unroll
            for (int gi = 0; gi < 4; gi++) {
                uint32_t b0a, b1a, b0b, b1b;
                ldsm_x4_t(b0a, b1a, b0b, b1b, vk + gi * 32);
                mma_f16(oacc[2 * gi],     a, b0a, b1a);
                mma_f16(oacc[2 * gi + 1], a, b0b, b1b);
            }
        }
    }

    // ---- finalize: /l, write ctx bf16 [B,S,D]
    {
        const int rp = warp * 16 + (lane >> 2);
        const float il0 = 1.f / lacc[0];   // row rp sum
        const float il1 = 1.f / lacc[2];   // row rp+8 sum
#pragma unroll
        for (int in = 0; in < 8; in++) {
            int c = in * 8 + 2 * (lane & 3);
            size_t base = ((size_t)b * SEQ + q0 + rp) * DMODEL + h * DHEAD + c;
            *(uint32_t*)(ctx + base) =
                pack_bf16(oacc[in][0] * il0, oacc[in][1] * il0);
            *(uint32_t*)(ctx + base + (size_t)8 * DMODEL) =
                pack_bf16(oacc[in][2] * il1, oacc[in][3] * il1);
        }
    }
}

// ---------------- residual + LayerNorm ---------------------------------------
__global__ __launch_bounds__(256) void ln_kernel(
    const float* __restrict__ hbuf, const float* __restrict__ x,
    const float* __restrict__ gamma, const float* __restrict__ beta,
    float* __restrict__ out)
{
    const int row = blockIdx.x;
    const int tid = threadIdx.x;
    const int lane = tid & 31, warp = tid >> 5;

    const float4* hp = (const float4*)(hbuf + (size_t)row * DMODEL);
    const float4* xp = (const float4*)(x + (size_t)row * DMODEL);
    float4 hv = hp[tid], xv = xp[tid];
    float4 y = make_float4(hv.x + xv.x, hv.y + xv.y, hv.z + xv.z, hv.w + xv.w);

    float s  = y.x + y.y + y.z + y.w;
    float sq = y.x * y.x + y.y * y.y + y.z * y.z + y.w * y.w;
#pragma unroll
    for (int o = 16; o; o >>= 1) {
        s  += __shfl_xor_sync(0xffffffffu, s, o);
        sq += __shfl_xor_sync(0xffffffffu, sq, o);
    }
    __shared__ float ss[8], ssq[8];
    if (lane == 0) { ss[warp] = s; ssq[warp] = sq; }
    __syncthreads();
    if (warp == 0) {
        s  = (lane < 8) ? ss[lane]  : 0.f;
        sq = (lane < 8) ? ssq[lane] : 0.f;
#pragma unroll
        for (int o = 4; o; o >>= 1) {
            s  += __shfl_xor_sync(0xffffffffu, s, o);
            sq += __shfl_xor_sync(0xffffffffu, sq, o);
        }
        if (lane == 0) { ss[0] = s; ssq[0] = sq; }
    }
    __syncthreads();
    s = ss[0]; sq = ssq[0];

    const float mu   = s * (1.f / DMODEL);
    const float var  = sq * (1.f / DMODEL) - mu * mu;
    const float rstd = rsqrtf(var + 1e-12f);

    float4 g = ((const float4*)gamma)[tid];
    float4 bt = ((const float4*)beta)[tid];
    float4 o;
    o.x = (y.x - mu) * rstd * g.x + bt.x;
    o.y = (y.y - mu) * rstd * g.y + bt.y;
    o.z = (y.z - mu) * rstd * g.z + bt.z;
    o.w = (y.w - mu) * rstd * g.w + bt.w;
    ((float4*)(out + (size_t)row * DMODEL))[tid] = o;
}

// ---------------- launch ------------------------------------------------------
extern "C" void kernel_launch(void* const* d_in, const int* in_sizes, int n_in,
                              void* d_out, int out_size)
{
    const float* x    = (const float*)d_in[0];
    const float* mask = (const float*)d_in[1];
    const float* Wq   = (const float*)d_in[2];
    const float* bq   = (const float*)d_in[3];
    const float* Wk   = (const float*)d_in[4];
    const float* bk   = (const float*)d_in[5];
    const float* Wv   = (const float*)d_in[6];
    const float* bv   = (const float*)d_in[7];
    const float* Wo   = (const float*)d_in[8];
    const float* bo   = (const float*)d_in[9];
    const float* gam  = (const float*)d_in[10];
    const float* bet  = (const float*)d_in[11];
    float* out = (float*)d_out;

    __nv_bfloat16 *pxb, *pQ, *pK, *pC, *pWt;
    __half *pV;
    float *pH, *pM;
    cudaGetSymbolAddress((void**)&pxb, g_xb);
    cudaGetSymbolAddress((void**)&pQ,  g_Qb);
    cudaGetSymbolAddress((void**)&pK,  g_Kb);
    cudaGetSymbolAddress((void**)&pV,  g_Vh);
    cudaGetSymbolAddress((void**)&pC,  g_ctxb);
    cudaGetSymbolAddress((void**)&pWt, g_Wtb);
    cudaGetSymbolAddress((void**)&pH,  g_h);
    cudaGetSymbolAddress((void**)&pM,  g_msc);
    __nv_bfloat16* Wto = pWt + (size_t)3 * DMODEL * DMODEL;

    cvt_kernel<<<MTOT * DMODEL / 4 / 256, 256>>>(x, (__nv_bfloat162*)pxb);
    mask_kernel<<<BATCH * SEQ / 256, 256>>>(mask, pM);
    tr_kernel<<<dim3(32, 32, 4), dim3(32, 8)>>>(Wq, Wk, Wv, Wo, pWt);

    const float qsc = 0.125f * 1.4426950408889634f;   // fold log2e into Q

    // fused QKV: grid.z picks weight/bias/output (z==2 emits fp16 V)
    gemm_bf16<<<dim3(DMODEL / GBN, MTOT / GBM, 3), 256>>>(
        pxb, pWt, bq, bk, bv, pQ, pK, pV, 1, qsc);

    attn_kernel<<<dim3(SEQ / AQ, NHEAD, BATCH), 256>>>(pQ, pK, pV, pM, pC);

    // O-projection (grid.z=1, weight slot 0 = Wto)
    gemm_bf16<<<dim3(DMODEL / GBN, MTOT / GBM, 1), 256>>>(
        pC, Wto, bo, bo, bo, pH, pH, pH, 0, 1.0f);

    ln_kernel<<<MTOT, 256>>>(pH, x, gam, bet, out);
}